// round 12
// baseline (speedup 1.0000x reference)
#include <cuda_runtime.h>
#include <cuda_bf16.h>
#include <cstdint>
#include <math.h>

// Problem dims
#define B_  64
#define L_  196
#define D_  2048
#define I_  512
#define M_  (B_ * L_)   // 12544

// Scratch (allocation-free: __device__ globals)
__device__ float g_hs [B_ * I_];          // hs_shaped + b_h + b_f   [B, I]
__device__ float g_t  [(size_t)M_ * I_];  // fv@W_f + bias (tf32)    [B*L, I]
__device__ float g_Wft[(size_t)I_ * D_];  // W_f^T (tf32)            [I, D]
__device__ float g_Wat[(size_t)D_ * I_];  // W_a^T (tf32)            [D, I]

// ---------------------------------------------------------------------------
// helpers
// ---------------------------------------------------------------------------
__device__ __forceinline__ uint32_t smem_u32(const void* p) {
    uint32_t a;
    asm("{ .reg .u64 t; cvta.to.shared.u64 t, %1; cvt.u32.u64 %0, t; }"
        : "=r"(a) : "l"(p));
    return a;
}

// round-to-nearest to tf32 (keep top 19 bits)
__device__ __forceinline__ float to_tf32(float v) {
    uint32_t u = __float_as_uint(v);
    u = (u + 0x1000u) & 0xFFFFE000u;
    return __uint_as_float(u);
}

#define MMA_TF32(c, a, b) \
    asm volatile("mma.sync.aligned.m16n8k8.row.col.f32.tf32.tf32.f32 " \
        "{%0,%1,%2,%3}, {%4,%5,%6,%7}, {%8,%9}, {%0,%1,%2,%3};" \
        : "+f"((c)[0]), "+f"((c)[1]), "+f"((c)[2]), "+f"((c)[3]) \
        : "r"((a)[0]), "r"((a)[1]), "r"((a)[2]), "r"((a)[3]), \
          "r"((b)[0]), "r"((b)[1]))

#define CP_ASYNC16(saddr, gptr) \
    asm volatile("cp.async.cg.shared.global [%0], [%1], 16;" \
                 :: "r"(saddr), "l"(gptr) : "memory")

// 4-matrix ldmatrix (b16 view of 8x4 f32 submatrices)
#define LDSM4(r, addr) \
    asm volatile("ldmatrix.sync.aligned.m8n8.x4.shared.b16 {%0,%1,%2,%3}, [%4];" \
        : "=r"((r)[0]), "=r"((r)[1]), "=r"((r)[2]), "=r"((r)[3]) : "r"(addr))

// ---------------------------------------------------------------------------
// Kernel A: g_hs[b,i] = b_f[i] + b_h[i] + sum_k hidden[b,k] * W_h[k,i]
// ---------------------------------------------------------------------------
__global__ __launch_bounds__(128)
void hs_kernel(const float* __restrict__ hidden,
               const float* __restrict__ W_h,
               const float* __restrict__ b_h,
               const float* __restrict__ b_f,
               float* __restrict__ out)
{
    __shared__ float h[I_];
    const int b = blockIdx.x;
    for (int k = threadIdx.x; k < I_; k += 128)
        h[k] = hidden[b * I_ + k];
    __syncthreads();

    const int i = blockIdx.y * 128 + threadIdx.x;
    float acc = b_h[i] + b_f[i];
    #pragma unroll 8
    for (int k = 0; k < I_; k++)
        acc = fmaf(h[k], W_h[(size_t)k * I_ + i], acc);
    out[b * I_ + i] = acc;
}

// ---------------------------------------------------------------------------
// Transpose + tf32 round: in[R][C] -> out[C][R]
// ---------------------------------------------------------------------------
__global__ __launch_bounds__(256)
void transpose_k(const float* __restrict__ in, float* __restrict__ out,
                 int R, int Cc)
{
    __shared__ float t[32][33];
    const int bx = blockIdx.x * 32;
    const int by = blockIdx.y * 32;
    const int x = threadIdx.x, y = threadIdx.y;
    #pragma unroll
    for (int i = 0; i < 32; i += 8)
        t[y + i][x] = in[(size_t)(by + y + i) * Cc + bx + x];
    __syncthreads();
    #pragma unroll
    for (int i = 0; i < 32; i += 8)
        out[(size_t)(bx + y + i) * R + by + x] = to_tf32(t[x][y + i]);
}

// ---------------------------------------------------------------------------
// tf32 mma.sync GEMM, K-split warp pairs:
// CTA 128x128x32, 512 threads = 16 warps = 8 pairs. Pair q owns 64x32
// quadrant; kh=0 computes ks{0,1}, kh=1 computes ks{2,3}. Halves LDSM
// traffic per warp (smem crossbar is the binder). Merge partials via smem
// in the epilogue. 3 cp.async stages (96KB), 1 CTA/SM (RF-limited).
// ---------------------------------------------------------------------------
#define NSTAGE 3
#define STAGE_BYTES 32768           // A 16KB + B 16KB
#define SMEM_BYTES (NSTAGE * STAGE_BYTES)

template <int TAG>
__global__ __launch_bounds__(512, 1)
void gemm_tc(int M, int N, int K,
             const float* __restrict__ A,
             const float* __restrict__ Bt,
             float* __restrict__ C,
             const float* __restrict__ bias,
             const float* __restrict__ rowBias,
             int rowsPerBatch, int cvtOut)
{
    extern __shared__ __align__(128) char smem[];
    const uint32_t sbase = smem_u32(smem);
    const int tid = threadIdx.x;
    const int wid = tid >> 5;
    const int lid = tid & 31;
    const int g   = lid >> 2;      // 0..7
    const int t4  = lid & 3;       // 0..3

    const int q  = wid & 7;        // quadrant id (8 quadrants of 64x32)
    const int kh = wid >> 3;       // k-half: 0 -> ks{0,1}, 1 -> ks{2,3}
    const int m0 = (q >> 2) * 64;
    const int n0 = (q & 3) * 32;

    const int crow = blockIdx.y, ccol = blockIdx.x;
    const float* Ab = A  + (size_t)crow * 128 * K;
    const float* Bb = Bt + (size_t)ccol * 128 * K;

    // ldmatrix lane-address bases (within a stage); addr(ks) = base ^ (ks<<5)
    uint32_t aOff[4], bOff[2];
    {
        const int arow_l = lid & 15;
        const uint32_t ahi = (uint32_t)(lid >> 4) << 4;
        #pragma unroll
        for (int mt = 0; mt < 4; mt++) {
            const int row = m0 + mt * 16 + arow_l;
            aOff[mt] = row * 128 + (ahi ^ ((row & 7) << 4));
        }
        const int brow_l = (lid & 7) + ((lid >> 4) << 3);
        const uint32_t bhi = (uint32_t)((lid >> 3) & 1) << 4;
        #pragma unroll
        for (int j = 0; j < 2; j++) {
            const int row = n0 + j * 16 + brow_l;
            bOff[j] = row * 128 + (bhi ^ ((row & 7) << 4));
        }
    }

    // Precomputed gmem->smem copy slots (512 threads: 2 A + 2 B each)
    uint32_t swzA[2], swzB[2];
    const float *ag[2], *bg[2];
    #pragma unroll
    for (int it = 0; it < 2; it++) {
        const int j = tid + it * 512;       // 0..1023 -> 128 rows x 8 chunks
        const int row = j >> 3, c4 = j & 7;
        const uint32_t swz = row * 128 + ((c4 << 4) ^ ((row & 7) << 4));
        swzA[it] = swz;  ag[it] = Ab + (size_t)row * K + c4 * 4;
        swzB[it] = swz;  bg[it] = Bb + (size_t)row * K + c4 * 4;
    }

    float cfr[4][4][4];
    #pragma unroll
    for (int mt = 0; mt < 4; mt++)
        #pragma unroll
        for (int nt = 0; nt < 4; nt++)
            #pragma unroll
            for (int qq = 0; qq < 4; qq++) cfr[mt][nt][qq] = 0.0f;

    const int nk = K >> 5;

    auto load_stage = [&](int ch, int s) {
        const int kc = ch * 32;
        const uint32_t sA = sbase + s * STAGE_BYTES;
        const uint32_t sB = sA + 16384;
        #pragma unroll
        for (int it = 0; it < 2; it++) {
            CP_ASYNC16(sA + swzA[it], ag[it] + kc);
            CP_ASYNC16(sB + swzB[it], bg[it] + kc);
        }
    };

    load_stage(0, 0);
    asm volatile("cp.async.commit_group;" ::: "memory");
    load_stage(1, 1);
    asm volatile("cp.async.commit_group;" ::: "memory");

    uint32_t af[2][16], bf[2][8];

    int s = 0;
    for (int ch = 0; ch < nk; ch++) {
        asm volatile("cp.async.wait_group 1;" ::: "memory");
        __syncthreads();
        const int s2 = (s + 2 >= NSTAGE) ? s - 1 : s + 2;
        if (ch + 2 < nk) load_stage(ch + 2, s2);
        asm volatile("cp.async.commit_group;" ::: "memory");

        const uint32_t sAa = sbase + s * STAGE_BYTES;
        const uint32_t sBa = sAa + 16384;

        auto load_frags = [&](int ks, int p) {
            const uint32_t kx = ks << 5;
            #pragma unroll
            for (int mt = 0; mt < 4; mt++)
                LDSM4(&af[p][mt * 4], sAa + (aOff[mt] ^ kx));
            #pragma unroll
            for (int j = 0; j < 2; j++)
                LDSM4(&bf[p][j * 4], sBa + (bOff[j] ^ kx));
        };

        const int ks0 = kh * 2;
        load_frags(ks0, 0);
        load_frags(ks0 + 1, 1);
        #pragma unroll
        for (int k2 = 0; k2 < 2; k2++) {
            #pragma unroll
            for (int mt = 0; mt < 4; mt++)
                #pragma unroll
                for (int nt = 0; nt < 4; nt++)
                    MMA_TF32(cfr[mt][nt], &af[k2][mt*4], &bf[k2][nt*2]);
        }
        s = (s + 1 >= NSTAGE) ? 0 : s + 1;
    }

    // -------- pair merge: kh=0 stores partials to smem, kh=1 adds ---------
    __syncthreads();                         // all frag reads of stages done
    // quadrant block: 32 lanes x 64 floats = 8KB, lane-major float4 slots:
    // addr = q*8192 + (i4*32 + lid)*16   (conflict-free STS/LDS.128)
    {
        float4* cf4 = reinterpret_cast<float4*>(&cfr[0][0][0]);
        float4* ms  = reinterpret_cast<float4*>(smem);
        if (kh == 0) {
            #pragma unroll
            for (int i4 = 0; i4 < 16; i4++)
                ms[q * 512 + i4 * 32 + lid] = cf4[i4];
        }
    }
    __syncthreads();
    if (kh == 1) {
        const float4* ms = reinterpret_cast<const float4*>(smem);
        float4* cf4 = reinterpret_cast<float4*>(&cfr[0][0][0]);
        #pragma unroll
        for (int i4 = 0; i4 < 16; i4++) {
            const float4 v = ms[q * 512 + i4 * 32 + lid];
            cf4[i4].x += v.x; cf4[i4].y += v.y;
            cf4[i4].z += v.z; cf4[i4].w += v.w;
        }

        // Epilogue: thread owns rows (m0+mt*16+g, +8), cols n0+nt*8+t4*2
        #pragma unroll
        for (int mt = 0; mt < 4; mt++) {
            #pragma unroll
            for (int half = 0; half < 2; half++) {
                const int ml = m0 + mt * 16 + g + half * 8;
                const size_t gm = (size_t)crow * 128 + ml;
                const float* rp = rowBias
                    ? rowBias + (gm / rowsPerBatch) * (size_t)N
                      + (size_t)ccol * 128
                    : nullptr;
                float* Crow = C + gm * N + (size_t)ccol * 128;
                #pragma unroll
                for (int nt = 0; nt < 4; nt++) {
                    const int cl = n0 + nt * 8 + t4 * 2;
                    float v0 = cfr[mt][nt][half * 2 + 0];
                    float v1 = cfr[mt][nt][half * 2 + 1];
                    if (bias) { v0 += bias[(size_t)ccol * 128 + cl];
                                v1 += bias[(size_t)ccol * 128 + cl + 1]; }
                    if (rp)   { v0 += rp[cl]; v1 += rp[cl + 1]; }
                    if (cvtOut) { v0 = to_tf32(v0); v1 = to_tf32(v1); }
                    *(float2*)(Crow + cl) = make_float2(v0, v1);
                }
            }
        }
    }
}

// ---------------------------------------------------------------------------
// Tiled softmax over L + z.  One CTA per (b, 128-d tile); e tile staged in
// smem; single exp per element.  In-place: e and alpha are the same buffer.
// ---------------------------------------------------------------------------
#define SMX_SMEM (L_ * 128 * 4)     // 100352 bytes

__global__ __launch_bounds__(256, 2)
void softmax_z_kernel(float* __restrict__ e_alpha,
                      const float* __restrict__ fv,
                      float* __restrict__ z)
{
    extern __shared__ float es[];           // [196][128]
    __shared__ float red[2][128];

    const int b  = blockIdx.y;
    const int d0 = blockIdx.x * 128;
    const int tid = threadIdx.x;

    float* Eb = e_alpha + (size_t)b * L_ * D_ + d0;
    const float* Fb = fv + (size_t)b * L_ * D_ + d0;

    // load tile, coalesced
    #pragma unroll 7
    for (int i = tid; i < L_ * 128; i += 256) {
        const int r = i >> 7, c = i & 127;
        es[i] = Eb[(size_t)r * D_ + c];
    }
    __syncthreads();

    const int col = tid & 127, half = tid >> 7;
    const int r0 = half * 98;

    // pass A: max over this half's 98 rows
    float m = -INFINITY;
    #pragma unroll 7
    for (int r = 0; r < 98; r++)
        m = fmaxf(m, es[(r0 + r) * 128 + col]);
    red[half][col] = m;
    __syncthreads();
    m = fmaxf(red[0][col], red[1][col]);
    __syncthreads();                        // red reuse guard

    // pass B: exp + sum, overwrite smem with un-normalized a
    float sum = 0.0f;
    #pragma unroll 7
    for (int r = 0; r < 98; r++) {
        const int idx = (r0 + r) * 128 + col;
        const float a = __expf(es[idx] - m);
        es[idx] = a;
        sum += a;
    }
    red[half][col] = sum;
    __syncthreads();
    const float inv = 1.0f / (red[0][col] + red[1][col]);
    __syncthreads();                        // red reuse guard

    // pass C: normalized write-out + z accumulation
    float zz = 0.0f;
    #pragma unroll 7
    for (int r = 0; r < 98; r++) {
        const int rr = r0 + r;
        const float a = es[rr * 128 + col] * inv;
        Eb[(size_t)rr * D_ + col] = a;
        zz = fmaf(a, Fb[(size_t)rr * D_ + col], zz);
    }
    red[half][col] = zz;
    __syncthreads();
    if (half == 0)
        z[(size_t)b * D_ + d0 + col] = red[0][col] + red[1][col];
}

// ---------------------------------------------------------------------------
// kernel_launch
// ---------------------------------------------------------------------------
extern "C" void kernel_launch(void* const* d_in, const int* in_sizes, int n_in,
                              void* d_out, int out_size)
{
    const float* fv     = (const float*)d_in[0];
    const float* hidden = (const float*)d_in[1];
    const float* W_f    = (const float*)d_in[2];
    const float* b_f    = (const float*)d_in[3];
    const float* W_h    = (const float*)d_in[4];
    const float* b_h    = (const float*)d_in[5];
    const float* W_a    = (const float*)d_in[6];
    const float* b_a    = (const float*)d_in[7];

    float* z     = (float*)d_out;
    float* alpha = z + (size_t)B_ * D_;

    float *hsPtr, *tPtr, *WftPtr, *WatPtr;
    cudaGetSymbolAddress((void**)&hsPtr,  g_hs);
    cudaGetSymbolAddress((void**)&tPtr,   g_t);
    cudaGetSymbolAddress((void**)&WftPtr, g_Wft);
    cudaGetSymbolAddress((void**)&WatPtr, g_Wat);

    cudaFuncSetAttribute(gemm_tc<1>, cudaFuncAttributeMaxDynamicSharedMemorySize,
                         SMEM_BYTES);
    cudaFuncSetAttribute(gemm_tc<2>, cudaFuncAttributeMaxDynamicSharedMemorySize,
                         SMEM_BYTES);
    cudaFuncSetAttribute(softmax_z_kernel,
                         cudaFuncAttributeMaxDynamicSharedMemorySize, SMX_SMEM);

    // 0) transpose weights to K-major + tf32 round
    transpose_k<<<dim3(I_ / 32, D_ / 32), dim3(32, 8)>>>(W_f, WftPtr, D_, I_);
    transpose_k<<<dim3(D_ / 32, I_ / 32), dim3(32, 8)>>>(W_a, WatPtr, I_, D_);

    // 1) hs = hidden @ W_h + b_h + b_f
    hs_kernel<<<dim3(B_, I_ / 128), 128>>>(hidden, W_h, b_h, b_f, hsPtr);

    // 2) t = fv @ W_f + hs[b]   M=12544, N=512, K=2048  (tf32-rounded out)
    gemm_tc<1><<<dim3(I_ / 128, M_ / 128), 512, SMEM_BYTES>>>(
        M_, I_, D_, fv, WftPtr, tPtr, nullptr, hsPtr, L_, 1);

    // 3) e = t @ W_a + b_a      M=12544, N=2048, K=512  (into alpha region)
    gemm_tc<2><<<dim3(D_ / 128, M_ / 128), 512, SMEM_BYTES>>>(
        M_, D_, I_, tPtr, WatPtr, alpha, b_a, nullptr, 1, 0);

    // 4) tiled softmax over L + z
    softmax_z_kernel<<<dim3(D_ / 128, B_), 256, SMX_SMEM>>>(alpha, fv, z);
}

// round 13
// speedup vs baseline: 1.1070x; 1.1070x over previous
#include <cuda_runtime.h>
#include <cuda_bf16.h>
#include <cstdint>
#include <math.h>

// Problem dims
#define B_  64
#define L_  196
#define D_  2048
#define I_  512
#define M_  (B_ * L_)   // 12544

// Scratch (allocation-free: __device__ globals)
__device__ float g_hs [B_ * I_];          // hs_shaped + b_h + b_f   [B, I]
__device__ float g_t  [(size_t)M_ * I_];  // fv@W_f + bias (tf32)    [B*L, I]
__device__ float g_Wft[(size_t)I_ * D_];  // W_f^T (tf32)            [I, D]
__device__ float g_Wat[(size_t)D_ * I_];  // W_a^T (tf32)            [D, I]

// ---------------------------------------------------------------------------
// helpers
// ---------------------------------------------------------------------------
__device__ __forceinline__ uint32_t smem_u32(const void* p) {
    uint32_t a;
    asm("{ .reg .u64 t; cvta.to.shared.u64 t, %1; cvt.u32.u64 %0, t; }"
        : "=r"(a) : "l"(p));
    return a;
}

// round-to-nearest to tf32 (keep top 19 bits)
__device__ __forceinline__ float to_tf32(float v) {
    uint32_t u = __float_as_uint(v);
    u = (u + 0x1000u) & 0xFFFFE000u;
    return __uint_as_float(u);
}

#define MMA_TF32(c, a, b) \
    asm volatile("mma.sync.aligned.m16n8k8.row.col.f32.tf32.tf32.f32 " \
        "{%0,%1,%2,%3}, {%4,%5,%6,%7}, {%8,%9}, {%0,%1,%2,%3};" \
        : "+f"((c)[0]), "+f"((c)[1]), "+f"((c)[2]), "+f"((c)[3]) \
        : "r"((a)[0]), "r"((a)[1]), "r"((a)[2]), "r"((a)[3]), \
          "r"((b)[0]), "r"((b)[1]))

#define CP_ASYNC16(saddr, gptr) \
    asm volatile("cp.async.cg.shared.global [%0], [%1], 16;" \
                 :: "r"(saddr), "l"(gptr) : "memory")

// cp.async completion -> mbarrier arrive (no pending-count increment)
#define CPASYNC_MBAR_ARRIVE(addr) \
    asm volatile("cp.async.mbarrier.arrive.noinc.shared.b64 [%0];" \
                 :: "r"(addr) : "memory")

#define MBAR_INIT(addr, cnt) \
    asm volatile("mbarrier.init.shared.b64 [%0], %1;" \
                 :: "r"(addr), "r"(cnt) : "memory")

#define MBAR_ARRIVE(addr) \
    asm volatile("mbarrier.arrive.shared.b64 _, [%0];" \
                 :: "r"(addr) : "memory")

__device__ __forceinline__ void mbar_wait(uint32_t addr, uint32_t parity) {
    uint32_t done;
    asm volatile("{\n\t.reg .pred p;\n\t"
        "mbarrier.try_wait.parity.acquire.cta.shared::cta.b64 p, [%1], %2;\n\t"
        "selp.b32 %0, 1, 0, p;\n\t}"
        : "=r"(done) : "r"(addr), "r"(parity) : "memory");
    while (!done) {
        asm volatile("{\n\t.reg .pred p;\n\t"
            "mbarrier.try_wait.parity.acquire.cta.shared::cta.b64 p, [%1], %2, 0x989680;\n\t"
            "selp.b32 %0, 1, 0, p;\n\t}"
            : "=r"(done) : "r"(addr), "r"(parity) : "memory");
    }
}

// 4-matrix ldmatrix (b16 view of 8x4 f32 submatrices)
#define LDSM4(r, addr) \
    asm volatile("ldmatrix.sync.aligned.m8n8.x4.shared.b16 {%0,%1,%2,%3}, [%4];" \
        : "=r"((r)[0]), "=r"((r)[1]), "=r"((r)[2]), "=r"((r)[3]) : "r"(addr))

// ---------------------------------------------------------------------------
// Kernel A: g_hs[b,i] = b_f[i] + b_h[i] + sum_k hidden[b,k] * W_h[k,i]
// ---------------------------------------------------------------------------
__global__ __launch_bounds__(128)
void hs_kernel(const float* __restrict__ hidden,
               const float* __restrict__ W_h,
               const float* __restrict__ b_h,
               const float* __restrict__ b_f,
               float* __restrict__ out)
{
    __shared__ float h[I_];
    const int b = blockIdx.x;
    for (int k = threadIdx.x; k < I_; k += 128)
        h[k] = hidden[b * I_ + k];
    __syncthreads();

    const int i = blockIdx.y * 128 + threadIdx.x;
    float acc = b_h[i] + b_f[i];
    #pragma unroll 8
    for (int k = 0; k < I_; k++)
        acc = fmaf(h[k], W_h[(size_t)k * I_ + i], acc);
    out[b * I_ + i] = acc;
}

// ---------------------------------------------------------------------------
// Transpose + tf32 round: in[R][C] -> out[C][R]
// ---------------------------------------------------------------------------
__global__ __launch_bounds__(256)
void transpose_k(const float* __restrict__ in, float* __restrict__ out,
                 int R, int Cc)
{
    __shared__ float t[32][33];
    const int bx = blockIdx.x * 32;
    const int by = blockIdx.y * 32;
    const int x = threadIdx.x, y = threadIdx.y;
    #pragma unroll
    for (int i = 0; i < 32; i += 8)
        t[y + i][x] = in[(size_t)(by + y + i) * Cc + bx + x];
    __syncthreads();
    #pragma unroll
    for (int i = 0; i < 32; i += 8)
        out[(size_t)(bx + y + i) * R + by + x] = to_tf32(t[x][y + i]);
}

// ---------------------------------------------------------------------------
// tf32 mma.sync GEMM with mbarrier producer/consumer pipeline (no
// __syncthreads in mainloop -> warps decouple, no convoy).
// CTA 128x128x32, 3 stages, 256 threads (8 warps, 64x32), 2 CTAs/SM.
//   full[s]  (count 256): cp.async.mbarrier.arrive.noinc per thread
//   empty[s] (count 8):   lane-0 per warp arrives after last LDSM of stage
// ---------------------------------------------------------------------------
#define NSTAGE 3
#define STAGE_BYTES 32768           // A 16KB + B 16KB
#define SMEM_DATA 1024              // stages start here; mbarriers below
#define SMEM_BYTES (SMEM_DATA + NSTAGE * STAGE_BYTES)

template <int TAG>
__global__ __launch_bounds__(256, 2)
void gemm_tc(int M, int N, int K,
             const float* __restrict__ A,
             const float* __restrict__ Bt,
             float* __restrict__ C,
             const float* __restrict__ bias,
             const float* __restrict__ rowBias,
             int rowsPerBatch, int cvtOut)
{
    extern __shared__ __align__(128) char smem[];
    const uint32_t sbase = smem_u32(smem);
    const int tid = threadIdx.x;
    const int wid = tid >> 5;
    const int lid = tid & 31;
    const int g   = lid >> 2;      // 0..7
    const int t4  = lid & 3;       // 0..3

    const int m0 = (wid >> 2) * 64;
    const int n0 = (wid & 3) * 32;

    // mbarriers: full[s] at sbase + 8s, empty[s] at sbase + 24 + 8s
    const uint32_t mbF = sbase;
    const uint32_t mbE = sbase + 24;
    if (tid == 0) {
        #pragma unroll
        for (int s = 0; s < NSTAGE; s++) {
            MBAR_INIT(mbF + 8 * s, 256u);
            MBAR_INIT(mbE + 8 * s, 8u);
        }
    }
    __syncthreads();

    const int crow = blockIdx.y, ccol = blockIdx.x;
    const float* Ab = A  + (size_t)crow * 128 * K;
    const float* Bb = Bt + (size_t)ccol * 128 * K;

    // ldmatrix lane-address bases (within a stage); addr(ks) = base ^ (ks<<5)
    uint32_t aOff[4], bOff[2];
    {
        const int arow_l = lid & 15;
        const uint32_t ahi = (uint32_t)(lid >> 4) << 4;
        #pragma unroll
        for (int mt = 0; mt < 4; mt++) {
            const int row = m0 + mt * 16 + arow_l;
            aOff[mt] = row * 128 + (ahi ^ ((row & 7) << 4));
        }
        const int brow_l = (lid & 7) + ((lid >> 4) << 3);
        const uint32_t bhi = (uint32_t)((lid >> 3) & 1) << 4;
        #pragma unroll
        for (int j = 0; j < 2; j++) {
            const int row = n0 + j * 16 + brow_l;
            bOff[j] = row * 128 + (bhi ^ ((row & 7) << 4));
        }
    }

    // Precomputed gmem->smem copy slots
    uint32_t swz[4];
    const float *ag[4], *bg[4];
    #pragma unroll
    for (int it = 0; it < 4; it++) {
        const int j = tid + it * 256;
        const int row = j >> 3, c4 = j & 7;
        swz[it] = row * 128 + ((c4 << 4) ^ ((row & 7) << 4));
        ag[it] = Ab + (size_t)row * K + c4 * 4;
        bg[it] = Bb + (size_t)row * K + c4 * 4;
    }

    float cfr[4][4][4];
    #pragma unroll
    for (int mt = 0; mt < 4; mt++)
        #pragma unroll
        for (int nt = 0; nt < 4; nt++)
            #pragma unroll
            for (int q = 0; q < 4; q++) cfr[mt][nt][q] = 0.0f;

    const int nk = K >> 5;

    auto load_stage = [&](int ch, int s) {
        const int kc = ch * 32;
        const uint32_t sA = sbase + SMEM_DATA + s * STAGE_BYTES;
        const uint32_t sB = sA + 16384;
        #pragma unroll
        for (int it = 0; it < 4; it++) {
            CP_ASYNC16(sA + swz[it], ag[it] + kc);
            CP_ASYNC16(sB + swz[it], bg[it] + kc);
        }
    };

    // prologue: fill stages 0,1
    load_stage(0, 0);  CPASYNC_MBAR_ARRIVE(mbF + 0);
    load_stage(1, 1);  CPASYNC_MBAR_ARRIVE(mbF + 8);

    uint32_t af[2][16], bf[2][8];
    uint32_t par = 0;   // bit s: full parity; bit 4+s: empty parity

    auto body = [&](int ch, int sg) {
        const int sg2 = (sg + 2 >= NSTAGE) ? sg - 1 : sg + 2;
        // producer: refill stage sg2 with chunk ch+2
        if (ch + 2 < nk) {
            if (ch > 0) {           // first write to stage 2 needs no wait
                mbar_wait(mbE + 8 * sg2, (par >> (4 + sg2)) & 1u);
                par ^= 1u << (4 + sg2);
            }
            load_stage(ch + 2, sg2);
            CPASYNC_MBAR_ARRIVE(mbF + 8 * sg2);
        }
        // consumer: wait for stage sg data
        mbar_wait(mbF + 8 * sg, (par >> sg) & 1u);
        par ^= 1u << sg;

        const uint32_t sAa = sbase + SMEM_DATA + sg * STAGE_BYTES;
        const uint32_t sBa = sAa + 16384;

        auto load_frags = [&](int ks, int p) {
            const uint32_t kx = ks << 5;
            #pragma unroll
            for (int mt = 0; mt < 4; mt++)
                LDSM4(&af[p][mt * 4], sAa + (aOff[mt] ^ kx));
            #pragma unroll
            for (int j = 0; j < 2; j++)
                LDSM4(&bf[p][j * 4], sBa + (bOff[j] ^ kx));
        };

        load_frags(0, 0);
        #pragma unroll
        for (int ks = 0; ks < 4; ks++) {
            const int p = ks & 1;
            if (ks < 3) load_frags(ks + 1, p ^ 1);
            if (ks == 2) {          // all LDSM of this stage issued
                __syncwarp();
                if (lid == 0) MBAR_ARRIVE(mbE + 8 * sg);
            }
            #pragma unroll
            for (int mt = 0; mt < 4; mt++)
                #pragma unroll
                for (int nt = 0; nt < 4; nt++)
                    MMA_TF32(cfr[mt][nt], &af[p][mt*4], &bf[p][nt*2]);
        }
    };

    for (int cb = 0; cb < nk; cb += 3) {
        body(cb, 0);
        if (cb + 1 < nk) body(cb + 1, 1);
        if (cb + 2 < nk) body(cb + 2, 2);
    }

    // Epilogue: thread owns rows (m0+mt*16+g, +8), cols n0+nt*8+t4*2 (+1)
    #pragma unroll
    for (int mt = 0; mt < 4; mt++) {
        #pragma unroll
        for (int half = 0; half < 2; half++) {
            const int ml = m0 + mt * 16 + g + half * 8;
            const size_t gm = (size_t)crow * 128 + ml;
            const float* rp = rowBias
                ? rowBias + (gm / rowsPerBatch) * (size_t)N + (size_t)ccol * 128
                : nullptr;
            float* Crow = C + gm * N + (size_t)ccol * 128;
            #pragma unroll
            for (int nt = 0; nt < 4; nt++) {
                const int cl = n0 + nt * 8 + t4 * 2;
                float v0 = cfr[mt][nt][half * 2 + 0];
                float v1 = cfr[mt][nt][half * 2 + 1];
                if (bias) { v0 += bias[(size_t)ccol * 128 + cl];
                            v1 += bias[(size_t)ccol * 128 + cl + 1]; }
                if (rp)   { v0 += rp[cl]; v1 += rp[cl + 1]; }
                if (cvtOut) { v0 = to_tf32(v0); v1 = to_tf32(v1); }
                *(float2*)(Crow + cl) = make_float2(v0, v1);
            }
        }
    }
}

// ---------------------------------------------------------------------------
// Tiled softmax over L + z.  One CTA per (b, 128-d tile); e tile staged in
// smem; single exp per element.  In-place: e and alpha are the same buffer.
// ---------------------------------------------------------------------------
#define SMX_SMEM (L_ * 128 * 4)     // 100352 bytes

__global__ __launch_bounds__(256, 2)
void softmax_z_kernel(float* __restrict__ e_alpha,
                      const float* __restrict__ fv,
                      float* __restrict__ z)
{
    extern __shared__ float es[];           // [196][128]
    __shared__ float red[2][128];

    const int b  = blockIdx.y;
    const int d0 = blockIdx.x * 128;
    const int tid = threadIdx.x;

    float* Eb = e_alpha + (size_t)b * L_ * D_ + d0;
    const float* Fb = fv + (size_t)b * L_ * D_ + d0;

    // load tile, coalesced
    #pragma unroll 7
    for (int i = tid; i < L_ * 128; i += 256) {
        const int r = i >> 7, c = i & 127;
        es[i] = Eb[(size_t)r * D_ + c];
    }
    __syncthreads();

    const int col = tid & 127, half = tid >> 7;
    const int r0 = half * 98;

    // pass A: max over this half's 98 rows
    float m = -INFINITY;
    #pragma unroll 7
    for (int r = 0; r < 98; r++)
        m = fmaxf(m, es[(r0 + r) * 128 + col]);
    red[half][col] = m;
    __syncthreads();
    m = fmaxf(red[0][col], red[1][col]);
    __syncthreads();                        // red reuse guard

    // pass B: exp + sum, overwrite smem with un-normalized a
    float sum = 0.0f;
    #pragma unroll 7
    for (int r = 0; r < 98; r++) {
        const int idx = (r0 + r) * 128 + col;
        const float a = __expf(es[idx] - m);
        es[idx] = a;
        sum += a;
    }
    red[half][col] = sum;
    __syncthreads();
    const float inv = 1.0f / (red[0][col] + red[1][col]);
    __syncthreads();                        // red reuse guard

    // pass C: normalized write-out + z accumulation
    float zz = 0.0f;
    #pragma unroll 7
    for (int r = 0; r < 98; r++) {
        const int rr = r0 + r;
        const float a = es[rr * 128 + col] * inv;
        Eb[(size_t)rr * D_ + col] = a;
        zz = fmaf(a, Fb[(size_t)rr * D_ + col], zz);
    }
    red[half][col] = zz;
    __syncthreads();
    if (half == 0)
        z[(size_t)b * D_ + d0 + col] = red[0][col] + red[1][col];
}

// ---------------------------------------------------------------------------
// kernel_launch
// ---------------------------------------------------------------------------
extern "C" void kernel_launch(void* const* d_in, const int* in_sizes, int n_in,
                              void* d_out, int out_size)
{
    const float* fv     = (const float*)d_in[0];
    const float* hidden = (const float*)d_in[1];
    const float* W_f    = (const float*)d_in[2];
    const float* b_f    = (const float*)d_in[3];
    const float* W_h    = (const float*)d_in[4];
    const float* b_h    = (const float*)d_in[5];
    const float* W_a    = (const float*)d_in[6];
    const float* b_a    = (const float*)d_in[7];

    float* z     = (float*)d_out;
    float* alpha = z + (size_t)B_ * D_;

    float *hsPtr, *tPtr, *WftPtr, *WatPtr;
    cudaGetSymbolAddress((void**)&hsPtr,  g_hs);
    cudaGetSymbolAddress((void**)&tPtr,   g_t);
    cudaGetSymbolAddress((void**)&WftPtr, g_Wft);
    cudaGetSymbolAddress((void**)&WatPtr, g_Wat);

    cudaFuncSetAttribute(gemm_tc<1>, cudaFuncAttributeMaxDynamicSharedMemorySize,
                         SMEM_BYTES);
    cudaFuncSetAttribute(gemm_tc<2>, cudaFuncAttributeMaxDynamicSharedMemorySize,
                         SMEM_BYTES);
    cudaFuncSetAttribute(softmax_z_kernel,
                         cudaFuncAttributeMaxDynamicSharedMemorySize, SMX_SMEM);

    // 0) transpose weights to K-major + tf32 round
    transpose_k<<<dim3(I_ / 32, D_ / 32), dim3(32, 8)>>>(W_f, WftPtr, D_, I_);
    transpose_k<<<dim3(D_ / 32, I_ / 32), dim3(32, 8)>>>(W_a, WatPtr, I_, D_);

    // 1) hs = hidden @ W_h + b_h + b_f
    hs_kernel<<<dim3(B_, I_ / 128), 128>>>(hidden, W_h, b_h, b_f, hsPtr);

    // 2) t = fv @ W_f + hs[b]   M=12544, N=512, K=2048  (tf32-rounded out)
    gemm_tc<1><<<dim3(I_ / 128, M_ / 128), 256, SMEM_BYTES>>>(
        M_, I_, D_, fv, WftPtr, tPtr, nullptr, hsPtr, L_, 1);

    // 3) e = t @ W_a + b_a      M=12544, N=2048, K=512  (into alpha region)
    gemm_tc<2><<<dim3(D_ / 128, M_ / 128), 256, SMEM_BYTES>>>(
        M_, D_, I_, tPtr, WatPtr, alpha, b_a, nullptr, 1, 0);

    // 4) tiled softmax over L + z
    softmax_z_kernel<<<dim3(D_ / 128, B_), 256, SMX_SMEM>>>(alpha, fv, z);
}

// round 15
// speedup vs baseline: 1.1113x; 1.0039x over previous
#include <cuda_runtime.h>
#include <cuda_bf16.h>
#include <cstdint>
#include <math.h>

// Problem dims
#define B_  64
#define L_  196
#define D_  2048
#define I_  512
#define M_  (B_ * L_)   // 12544

// Scratch (allocation-free: __device__ globals)
__device__ float g_hs [B_ * I_];            // hs_shaped + b_h + b_f [B, I]
__device__ float g_t  [2 * (size_t)M_ * I_];// split-K partials / final t
__device__ float g_Wft[(size_t)I_ * D_];    // W_f^T (tf32)          [I, D]
__device__ float g_Wat[(size_t)D_ * I_];    // W_a^T (tf32)          [D, I]

// ---------------------------------------------------------------------------
// helpers
// ---------------------------------------------------------------------------
__device__ __forceinline__ uint32_t smem_u32(const void* p) {
    uint32_t a;
    asm("{ .reg .u64 t; cvta.to.shared.u64 t, %1; cvt.u32.u64 %0, t; }"
        : "=r"(a) : "l"(p));
    return a;
}

__device__ __forceinline__ float to_tf32(float v) {
    uint32_t u = __float_as_uint(v);
    u = (u + 0x1000u) & 0xFFFFE000u;
    return __uint_as_float(u);
}

#define MMA_TF32(c, a, b) \
    asm volatile("mma.sync.aligned.m16n8k8.row.col.f32.tf32.tf32.f32 " \
        "{%0,%1,%2,%3}, {%4,%5,%6,%7}, {%8,%9}, {%0,%1,%2,%3};" \
        : "+f"((c)[0]), "+f"((c)[1]), "+f"((c)[2]), "+f"((c)[3]) \
        : "r"((a)[0]), "r"((a)[1]), "r"((a)[2]), "r"((a)[3]), \
          "r"((b)[0]), "r"((b)[1]))

#define CP_ASYNC16(saddr, gptr) \
    asm volatile("cp.async.cg.shared.global [%0], [%1], 16;" \
                 :: "r"(saddr), "l"(gptr) : "memory")

#define CPASYNC_MBAR_ARRIVE(addr) \
    asm volatile("cp.async.mbarrier.arrive.noinc.shared.b64 [%0];" \
                 :: "r"(addr) : "memory")

#define MBAR_INIT(addr, cnt) \
    asm volatile("mbarrier.init.shared.b64 [%0], %1;" \
                 :: "r"(addr), "r"(cnt) : "memory")

#define MBAR_ARRIVE(addr) \
    asm volatile("mbarrier.arrive.shared.b64 _, [%0];" \
                 :: "r"(addr) : "memory")

__device__ __forceinline__ void mbar_wait(uint32_t addr, uint32_t parity) {
    uint32_t done;
    asm volatile("{\n\t.reg .pred p;\n\t"
        "mbarrier.try_wait.parity.acquire.cta.shared::cta.b64 p, [%1], %2;\n\t"
        "selp.b32 %0, 1, 0, p;\n\t}"
        : "=r"(done) : "r"(addr), "r"(parity) : "memory");
    while (!done) {
        asm volatile("{\n\t.reg .pred p;\n\t"
            "mbarrier.try_wait.parity.acquire.cta.shared::cta.b64 p, [%1], %2, 0x989680;\n\t"
            "selp.b32 %0, 1, 0, p;\n\t}"
            : "=r"(done) : "r"(addr), "r"(parity) : "memory");
    }
}

#define LDSM4(r, addr) \
    asm volatile("ldmatrix.sync.aligned.m8n8.x4.shared.b16 {%0,%1,%2,%3}, [%4];" \
        : "=r"((r)[0]), "=r"((r)[1]), "=r"((r)[2]), "=r"((r)[3]) : "r"(addr))

// ---------------------------------------------------------------------------
// Kernel A: g_hs[b,i] = b_f[i] + b_h[i] + sum_k hidden[b,k] * W_h[k,i]
// ---------------------------------------------------------------------------
__global__ __launch_bounds__(128)
void hs_kernel(const float* __restrict__ hidden,
               const float* __restrict__ W_h,
               const float* __restrict__ b_h,
               const float* __restrict__ b_f,
               float* __restrict__ out)
{
    __shared__ float h[I_];
    const int b = blockIdx.x;
    for (int k = threadIdx.x; k < I_; k += 128)
        h[k] = hidden[b * I_ + k];
    __syncthreads();

    const int i = blockIdx.y * 128 + threadIdx.x;
    float acc = b_h[i] + b_f[i];
    #pragma unroll 8
    for (int k = 0; k < I_; k++)
        acc = fmaf(h[k], W_h[(size_t)k * I_ + i], acc);
    out[b * I_ + i] = acc;
}

// ---------------------------------------------------------------------------
// Transpose + tf32 round: in[R][C] -> out[C][R]
// ---------------------------------------------------------------------------
__global__ __launch_bounds__(256)
void transpose_k(const float* __restrict__ in, float* __restrict__ out,
                 int R, int Cc)
{
    __shared__ float t[32][33];
    const int bx = blockIdx.x * 32;
    const int by = blockIdx.y * 32;
    const int x = threadIdx.x, y = threadIdx.y;
    #pragma unroll
    for (int i = 0; i < 32; i += 8)
        t[y + i][x] = in[(size_t)(by + y + i) * Cc + bx + x];
    __syncthreads();
    #pragma unroll
    for (int i = 0; i < 32; i += 8)
        out[(size_t)(bx + y + i) * R + by + x] = to_tf32(t[x][y + i]);
}

// ---------------------------------------------------------------------------
// Split-K reduce: t[i] = to_tf32(p0[i] + p1[i] + hs[batch(row)][col])
// (in-place: out == p0)
// ---------------------------------------------------------------------------
__global__ __launch_bounds__(256)
void reduce_split(const float* __restrict__ p0,
                  const float* __restrict__ p1,
                  const float* __restrict__ hs,
                  float* __restrict__ out)
{
    const size_t i4 = (size_t)blockIdx.x * 256 + threadIdx.x;  // float4 index
    const size_t i0 = i4 * 4;
    const int row = (int)(i0 >> 9);          // / I_ (512)
    const int col = (int)(i0 & 511);
    const float4 a = ((const float4*)p0)[i4];
    const float4 b = ((const float4*)p1)[i4];
    const float4 r = *(const float4*)(hs + (size_t)(row / L_) * I_ + col);
    float4 o;
    o.x = to_tf32(a.x + b.x + r.x);
    o.y = to_tf32(a.y + b.y + r.y);
    o.z = to_tf32(a.z + b.z + r.z);
    o.w = to_tf32(a.w + b.w + r.w);
    ((float4*)out)[i4] = o;
}

// ---------------------------------------------------------------------------
// tf32 mma.sync GEMM with mbarrier producer/consumer pipeline.
// CTA 128x128x(K/ksplit), 3 stages, 256 threads (8 warps, 64x32), 2 CTAs/SM.
// ksplit>1: blockIdx.z picks the K-slice; partial kz written to C + kz*M*N.
// ---------------------------------------------------------------------------
#define NSTAGE 3
#define STAGE_BYTES 32768           // A 16KB + B 16KB
#define SMEM_DATA 1024
#define SMEM_BYTES (SMEM_DATA + NSTAGE * STAGE_BYTES)

template <int TAG>
__global__ __launch_bounds__(256, 2)
void gemm_tc(int M, int N, int K,
             const float* __restrict__ A,
             const float* __restrict__ Bt,
             float* __restrict__ C,
             const float* __restrict__ bias,
             const float* __restrict__ rowBias,
             int rowsPerBatch, int cvtOut, int ksplit)
{
    extern __shared__ __align__(128) char smem[];
    const uint32_t sbase = smem_u32(smem);
    const int tid = threadIdx.x;
    const int wid = tid >> 5;
    const int lid = tid & 31;
    const int g   = lid >> 2;
    const int t4  = lid & 3;

    const int m0 = (wid >> 2) * 64;
    const int n0 = (wid & 3) * 32;

    const uint32_t mbF = sbase;
    const uint32_t mbE = sbase + 24;
    if (tid == 0) {
        #pragma unroll
        for (int s = 0; s < NSTAGE; s++) {
            MBAR_INIT(mbF + 8 * s, 256u);
            MBAR_INIT(mbE + 8 * s, 8u);
        }
    }
    __syncthreads();

    const int crow = blockIdx.y, ccol = blockIdx.x;
    const int kz = blockIdx.z;
    const int kLen = K / ksplit;
    const float* Ab = A  + (size_t)crow * 128 * K + (size_t)kz * kLen;
    const float* Bb = Bt + (size_t)ccol * 128 * K + (size_t)kz * kLen;
    float* Cb = C + (size_t)kz * M * N;

    uint32_t aOff[4], bOff[2];
    {
        const int arow_l = lid & 15;
        const uint32_t ahi = (uint32_t)(lid >> 4) << 4;
        #pragma unroll
        for (int mt = 0; mt < 4; mt++) {
            const int row = m0 + mt * 16 + arow_l;
            aOff[mt] = row * 128 + (ahi ^ ((row & 7) << 4));
        }
        const int brow_l = (lid & 7) + ((lid >> 4) << 3);
        const uint32_t bhi = (uint32_t)((lid >> 3) & 1) << 4;
        #pragma unroll
        for (int j = 0; j < 2; j++) {
            const int row = n0 + j * 16 + brow_l;
            bOff[j] = row * 128 + (bhi ^ ((row & 7) << 4));
        }
    }

    uint32_t swz[4];
    const float *ag[4], *bg[4];
    #pragma unroll
    for (int it = 0; it < 4; it++) {
        const int j = tid + it * 256;
        const int row = j >> 3, c4 = j & 7;
        swz[it] = row * 128 + ((c4 << 4) ^ ((row & 7) << 4));
        ag[it] = Ab + (size_t)row * K + c4 * 4;
        bg[it] = Bb + (size_t)row * K + c4 * 4;
    }

    float cfr[4][4][4];
    #pragma unroll
    for (int mt = 0; mt < 4; mt++)
        #pragma unroll
        for (int nt = 0; nt < 4; nt++)
            #pragma unroll
            for (int q = 0; q < 4; q++) cfr[mt][nt][q] = 0.0f;

    const int nk = kLen >> 5;

    auto load_stage = [&](int ch, int s) {
        const int kc = ch * 32;
        const uint32_t sA = sbase + SMEM_DATA + s * STAGE_BYTES;
        const uint32_t sB = sA + 16384;
        #pragma unroll
        for (int it = 0; it < 4; it++) {
            CP_ASYNC16(sA + swz[it], ag[it] + kc);
            CP_ASYNC16(sB + swz[it], bg[it] + kc);
        }
    };

    load_stage(0, 0);  CPASYNC_MBAR_ARRIVE(mbF + 0);
    load_stage(1, 1);  CPASYNC_MBAR_ARRIVE(mbF + 8);

    uint32_t af[2][16], bf[2][8];
    uint32_t par = 0;

    auto body = [&](int ch, int sg) {
        const int sg2 = (sg + 2 >= NSTAGE) ? sg - 1 : sg + 2;
        if (ch + 2 < nk) {
            if (ch > 0) {
                mbar_wait(mbE + 8 * sg2, (par >> (4 + sg2)) & 1u);
                par ^= 1u << (4 + sg2);
            }
            load_stage(ch + 2, sg2);
            CPASYNC_MBAR_ARRIVE(mbF + 8 * sg2);
        }
        mbar_wait(mbF + 8 * sg, (par >> sg) & 1u);
        par ^= 1u << sg;

        const uint32_t sAa = sbase + SMEM_DATA + sg * STAGE_BYTES;
        const uint32_t sBa = sAa + 16384;

        auto load_frags = [&](int ks, int p) {
            const uint32_t kx = ks << 5;
            #pragma unroll
            for (int mt = 0; mt < 4; mt++)
                LDSM4(&af[p][mt * 4], sAa + (aOff[mt] ^ kx));
            #pragma unroll
            for (int j = 0; j < 2; j++)
                LDSM4(&bf[p][j * 4], sBa + (bOff[j] ^ kx));
        };

        load_frags(0, 0);
        #pragma unroll
        for (int ks = 0; ks < 4; ks++) {
            const int p = ks & 1;
            if (ks < 3) load_frags(ks + 1, p ^ 1);
            if (ks == 2) {
                __syncwarp();
                if (lid == 0) MBAR_ARRIVE(mbE + 8 * sg);
            }
            #pragma unroll
            for (int mt = 0; mt < 4; mt++)
                #pragma unroll
                for (int nt = 0; nt < 4; nt++)
                    MMA_TF32(cfr[mt][nt], &af[p][mt*4], &bf[p][nt*2]);
        }
    };

    for (int cb = 0; cb < nk; cb += 3) {
        body(cb, 0);
        if (cb + 1 < nk) body(cb + 1, 1);
        if (cb + 2 < nk) body(cb + 2, 2);
    }

    #pragma unroll
    for (int mt = 0; mt < 4; mt++) {
        #pragma unroll
        for (int half = 0; half < 2; half++) {
            const int ml = m0 + mt * 16 + g + half * 8;
            const size_t gm = (size_t)crow * 128 + ml;
            const float* rp = rowBias
                ? rowBias + (gm / rowsPerBatch) * (size_t)N + (size_t)ccol * 128
                : nullptr;
            float* Crow = Cb + gm * N + (size_t)ccol * 128;
            #pragma unroll
            for (int nt = 0; nt < 4; nt++) {
                const int cl = n0 + nt * 8 + t4 * 2;
                float v0 = cfr[mt][nt][half * 2 + 0];
                float v1 = cfr[mt][nt][half * 2 + 1];
                if (bias) { v0 += bias[(size_t)ccol * 128 + cl];
                            v1 += bias[(size_t)ccol * 128 + cl + 1]; }
                if (rp)   { v0 += rp[cl]; v1 += rp[cl + 1]; }
                if (cvtOut) { v0 = to_tf32(v0); v1 = to_tf32(v1); }
                *(float2*)(Crow + cl) = make_float2(v0, v1);
            }
        }
    }
}

// ---------------------------------------------------------------------------
// Tiled softmax over L + z (unchanged champion)
// ---------------------------------------------------------------------------
#define SMX_SMEM (L_ * 128 * 4)

__global__ __launch_bounds__(256, 2)
void softmax_z_kernel(float* __restrict__ e_alpha,
                      const float* __restrict__ fv,
                      float* __restrict__ z)
{
    extern __shared__ float es[];
    __shared__ float red[2][128];

    const int b  = blockIdx.y;
    const int d0 = blockIdx.x * 128;
    const int tid = threadIdx.x;

    float* Eb = e_alpha + (size_t)b * L_ * D_ + d0;
    const float* Fb = fv + (size_t)b * L_ * D_ + d0;

    #pragma unroll 7
    for (int i = tid; i < L_ * 128; i += 256) {
        const int r = i >> 7, c = i & 127;
        es[i] = Eb[(size_t)r * D_ + c];
    }
    __syncthreads();

    const int col = tid & 127, half = tid >> 7;
    const int r0 = half * 98;

    float m = -INFINITY;
    #pragma unroll 7
    for (int r = 0; r < 98; r++)
        m = fmaxf(m, es[(r0 + r) * 128 + col]);
    red[half][col] = m;
    __syncthreads();
    m = fmaxf(red[0][col], red[1][col]);
    __syncthreads();

    float sum = 0.0f;
    #pragma unroll 7
    for (int r = 0; r < 98; r++) {
        const int idx = (r0 + r) * 128 + col;
        const float a = __expf(es[idx] - m);
        es[idx] = a;
        sum += a;
    }
    red[half][col] = sum;
    __syncthreads();
    const float inv = 1.0f / (red[0][col] + red[1][col]);
    __syncthreads();

    float zz = 0.0f;
    #pragma unroll 7
    for (int r = 0; r < 98; r++) {
        const int rr = r0 + r;
        const float a = es[rr * 128 + col] * inv;
        Eb[(size_t)rr * D_ + col] = a;
        zz = fmaf(a, Fb[(size_t)rr * D_ + col], zz);
    }
    red[half][col] = zz;
    __syncthreads();
    if (half == 0)
        z[(size_t)b * D_ + d0 + col] = red[0][col] + red[1][col];
}

// ---------------------------------------------------------------------------
// kernel_launch
// ---------------------------------------------------------------------------
extern "C" void kernel_launch(void* const* d_in, const int* in_sizes, int n_in,
                              void* d_out, int out_size)
{
    const float* fv     = (const float*)d_in[0];
    const float* hidden = (const float*)d_in[1];
    const float* W_f    = (const float*)d_in[2];
    const float* b_f    = (const float*)d_in[3];
    const float* W_h    = (const float*)d_in[4];
    const float* b_h    = (const float*)d_in[5];
    const float* W_a    = (const float*)d_in[6];
    const float* b_a    = (const float*)d_in[7];

    float* z     = (float*)d_out;
    float* alpha = z + (size_t)B_ * D_;

    float *hsPtr, *tPtr, *WftPtr, *WatPtr;
    cudaGetSymbolAddress((void**)&hsPtr,  g_hs);
    cudaGetSymbolAddress((void**)&tPtr,   g_t);   // [2][M, I]: partials; final in slice 0
    cudaGetSymbolAddress((void**)&WftPtr, g_Wft);
    cudaGetSymbolAddress((void**)&WatPtr, g_Wat);

    cudaFuncSetAttribute(gemm_tc<1>, cudaFuncAttributeMaxDynamicSharedMemorySize,
                         SMEM_BYTES);
    cudaFuncSetAttribute(gemm_tc<2>, cudaFuncAttributeMaxDynamicSharedMemorySize,
                         SMEM_BYTES);
    cudaFuncSetAttribute(softmax_z_kernel,
                         cudaFuncAttributeMaxDynamicSharedMemorySize, SMX_SMEM);

    // 0) transpose weights to K-major + tf32 round
    transpose_k<<<dim3(I_ / 32, D_ / 32), dim3(32, 8)>>>(W_f, WftPtr, D_, I_);
    transpose_k<<<dim3(D_ / 32, I_ / 32), dim3(32, 8)>>>(W_a, WatPtr, I_, D_);

    // 1) hs = hidden @ W_h + b_h + b_f
    hs_kernel<<<dim3(B_, I_ / 128), 128>>>(hidden, W_h, b_h, b_f, hsPtr);

    // 2) t partials (split-K x2): 784 CTAs -> 3 waves @88% util (was 2 @66%)
    gemm_tc<1><<<dim3(I_ / 128, M_ / 128, 2), 256, SMEM_BYTES>>>(
        M_, I_, D_, fv, WftPtr, tPtr, nullptr, nullptr, L_, 0, 2);

    // 2b) t = to_tf32(p0 + p1 + hs[b])   (in-place into slice 0)
    reduce_split<<<(M_ * I_) / 1024, 256>>>(tPtr, tPtr + (size_t)M_ * I_,
                                            hsPtr, tPtr);

    // 3) e = t @ W_a + b_a   (into alpha region)
    gemm_tc<2><<<dim3(D_ / 128, M_ / 128, 1), 256, SMEM_BYTES>>>(
        M_, D_, I_, tPtr, WatPtr, alpha, b_a, nullptr, 1, 0, 1);

    // 4) tiled softmax over L + z
    softmax_z_kernel<<<dim3(D_ / 128, B_), 256, SMX_SMEM>>>(alpha, fv, z);
}